// round 14
// baseline (speedup 1.0000x reference)
#include <cuda_runtime.h>

// ---------------------------------------------------------------------------
// IPB windowed inhibition attention, fp32. Round 14 (= R12 best point + fixes):
//  - Q/K eliminated: sim = x (W_q^T W_k) x^T; sigma folded into S1;
//    V' = x (W_out W_v)^T; 4x4 tiles everywhere; 5 CTAs/SM, 48-reg cap
//  - no constant bank / no memcpy node (uniform LDG on g_small)
//  - S4 reads W_m2a row-major via LDG.128 (was 128 strided LDG.32 warp-insts)
// One CTA per (window, B): 8192 CTAs x 256 threads.
// ---------------------------------------------------------------------------

#define TPB 256

namespace {
constexpr int H_STR = 256 * 28;
constexpr int B_STR = 256 * 256 * 28;
constexpr int STW = 60;     // sWT [28][60]

// layout (floats)
constexpr int OFF_XT  = 0;       // [28][64] x^T (plain)
constexpr int OFF_YT  = 1792;    // [28][64] y^T (swizzled)
constexpr int OFF_WT  = 3584;    // [28][60] permuted weights   (ends 5264)
constexpr int OFF_V   = 5264;    // [64][28] V'                 (ends 7056)
constexpr int OFF_SIM = 7056;    // [64][64] swizzled           (ends 11152)
constexpr int OFF_AT  = 0;       // attnT [64][64] alias (xT/yT dead after S2)
constexpr int OFF_SGQ = 11152;
constexpr int OFF_SGK = 11216;
constexpr int OFF_TH  = 11280;
constexpr int OFF_RED = 11344;
constexpr int SM_FLOATS = 11348;
constexpr int SM_BYTES  = SM_FLOATS * 4;   // 45392 B -> 5 CTAs/SM

// g_small layout
constexpr int GS_BOUT = 0;     // 28
constexpr int GS_WM1  = 32;    // 64
constexpr int GS_WM2B = 96;    // 64
constexpr int GS_BPCQ = 160;
constexpr int GS_BPCK = 161;
constexpr int GS_TOTAL = 176;

// W column blocks (permuted for single-float4 thread loads):
//  block1 (32 logical cols, cpos 0..7): c = cpos + 8*mm
//    c: 0..27 = M columns (y) | 28 sigma_q | 29 sigma_k | 30,31 pads
//    cp(c) = 4*(c % 8) + c/8
//  block2 (28 V' cols, cpos2 0..6): c2 = cpos2 + 7*mm, cp = 32 + 4*(c2%7) + c2/7
}

__device__ __align__(16) float g_WT[28 * STW];
__device__ __align__(16) float g_small[GS_TOTAL];

__global__ void __launch_bounds__(TPB) prep_kernel(
    const float* __restrict__ W_qk,   // [56,28]
    const float* __restrict__ W_v,    // [28,28]
    const float* __restrict__ W_out,  // [28,28]
    const float* __restrict__ b_out,  // [28]
    const float* __restrict__ W_pcq,  // [28]
    const float* __restrict__ b_pcq,  // [1]
    const float* __restrict__ W_pck,  // [28]
    const float* __restrict__ b_pck,  // [1]
    const float* __restrict__ W_m1,   // [64]
    const float* __restrict__ W_m2b)  // [64]
{
    const int gtid = blockIdx.x * TPB + threadIdx.x;
    const int gstep = gridDim.x * TPB;
    // M[e][f] = sum_r W_q[r][e] * W_k[r][f]  -> block1 col f
    for (int i = gtid; i < 784; i += gstep) {
        const int e = i / 28, f = i % 28;
        float acc = 0.f;
        #pragma unroll 7
        for (int r = 0; r < 28; r++)
            acc = fmaf(W_qk[r * 28 + e], W_qk[(28 + r) * 28 + f], acc);
        g_WT[e * STW + 4 * (f % 8) + (f / 8)] = acc;
    }
    // V' = W_out @ W_v  -> block2
    for (int i = gtid; i < 784; i += gstep) {
        const int c = i / 28, e = i % 28;
        float acc = 0.f;
        #pragma unroll 7
        for (int d = 0; d < 28; d++)
            acc = fmaf(W_out[c * 28 + d], W_v[d * 28 + e], acc);
        g_WT[e * STW + 32 + 4 * (c % 7) + (c / 7)] = acc;
    }
    // sigma columns (wx = W^T w_pc) + zero pads
    for (int i = gtid; i < 112; i += gstep) {
        const int e = i % 28, which = i / 28;
        if (which < 2) {
            const float* wp = (which == 0) ? W_pcq : W_pck;
            const int coff = (which == 0) ? 0 : 28;
            float acc = 0.f;
            #pragma unroll 7
            for (int c = 0; c < 28; c++)
                acc = fmaf(wp[c], W_qk[(coff + c) * 28 + e], acc);
            g_WT[e * STW + ((which == 0) ? 19 : 23)] = acc;  // cp(28)=19, cp(29)=23
        } else {
            g_WT[e * STW + ((which == 2) ? 27 : 31)] = 0.f;  // cp(30)=27, cp(31)=31
        }
    }
    // pack small vectors
    if (blockIdx.x == 0) {
        const int t = threadIdx.x;
        if (t < 28) g_small[GS_BOUT + t] = b_out[t];
        else if (t < 92)  g_small[GS_WM1  + t - 28] = W_m1[t - 28];
        else if (t < 156) g_small[GS_WM2B + t - 92] = W_m2b[t - 92];
        else if (t == 156) g_small[GS_BPCQ] = b_pcq[0];
        else if (t == 157) g_small[GS_BPCK] = b_pck[0];
    }
}

__global__ void __launch_bounds__(TPB, 5) ipb_kernel(
    const float* __restrict__ x,
    const float* __restrict__ W_m2a,  // [64,64] row-major
    float* __restrict__ out)
{
    extern __shared__ float sm[];
    float* sxT  = sm + OFF_XT;
    float* syT  = sm + OFF_YT;
    float* sWT  = sm + OFF_WT;
    float* sv   = sm + OFF_V;
    float* ssim = sm + OFF_SIM;
    float* satT = sm + OFF_AT;
    float* sigq = sm + OFF_SGQ;
    float* sigk = sm + OFF_SGK;
    float* sth  = sm + OFF_TH;
    float* sred = sm + OFF_RED;

    const int tid  = threadIdx.x;
    const int widx = blockIdx.x & 1023;
    const int Bi   = blockIdx.x >> 10;
    const int wh = widx >> 5, ww = widx & 31;
    const float* xbase = x + (size_t)Bi * B_STR + wh * 8 * H_STR + ww * 8 * 28;

    // ======== S0: x transpose + weight copy ========
    {
        {
            const int r = tid & 63, c4 = (tid >> 6) * 4;
            const float4 v = *(const float4*)(xbase + (r >> 3) * H_STR + (r & 7) * 28 + c4);
            sxT[(c4 + 0) * 64 + r] = v.x;
            sxT[(c4 + 1) * 64 + r] = v.y;
            sxT[(c4 + 2) * 64 + r] = v.z;
            sxT[(c4 + 3) * 64 + r] = v.w;
        }
        if (tid < 192) {
            const int i = tid + 256;
            const int r = i & 63, c4 = (i >> 6) * 4;
            const float4 v = *(const float4*)(xbase + (r >> 3) * H_STR + (r & 7) * 28 + c4);
            sxT[(c4 + 0) * 64 + r] = v.x;
            sxT[(c4 + 1) * 64 + r] = v.y;
            sxT[(c4 + 2) * 64 + r] = v.z;
            sxT[(c4 + 3) * 64 + r] = v.w;
        }
        ((float4*)sWT)[tid] = ((const float4*)g_WT)[tid];
        if (tid < 164)
            ((float4*)sWT)[tid + 256] = ((const float4*)g_WT)[tid + 256];
    }
    __syncthreads();

    // ======== S1: [y | sigma | V'] = x @ [M | wx | W_vo^T] ========
    // 240 units: u<128 block1 (t-fast), u>=128 block2 (V, cpos-fast)
    if (tid < 240) {
        if (tid < 128) {
            const int t16 = tid & 15, cpos = tid >> 4;   // cpos 0..7
            const int t4 = t16 * 4;
            const float* xb = sxT + t4;
            const float* wb = sWT + 4 * cpos;
            float4 acc[4] = {{0,0,0,0},{0,0,0,0},{0,0,0,0},{0,0,0,0}};
            #pragma unroll
            for (int k = 0; k < 28; k++) {
                const float4 a = *(const float4*)&xb[k * 64];
                const float4 w = *(const float4*)&wb[k * STW];
                #pragma unroll
                for (int mm = 0; mm < 4; mm++) {
                    const float wv = (mm == 0) ? w.x : (mm == 1) ? w.y : (mm == 2) ? w.z : w.w;
                    acc[mm].x = fmaf(a.x, wv, acc[mm].x);
                    acc[mm].y = fmaf(a.y, wv, acc[mm].y);
                    acc[mm].z = fmaf(a.z, wv, acc[mm].z);
                    acc[mm].w = fmaf(a.w, wv, acc[mm].w);
                }
            }
            #pragma unroll
            for (int mm = 0; mm < 4; mm++) {
                const int c = cpos + 8 * mm;
                const float* fa = (const float*)&acc[mm];
                if (c < 28) {
                    *(float4*)&syT[c * 64 + 4 * ((t16 ^ c) & 15)] = acc[mm];
                } else if (c == 28) {
                    const float bq = g_small[GS_BPCQ];
                    #pragma unroll
                    for (int tt = 0; tt < 4; tt++) sigq[t4 + tt] = fa[tt] + bq;
                } else if (c == 29) {
                    const float bk = g_small[GS_BPCK];
                    #pragma unroll
                    for (int tt = 0; tt < 4; tt++) sigk[t4 + tt] = fa[tt] + bk;
                }
            }
        } else {
            const int v = tid - 128;                     // 0..111
            const int cpos2 = v % 7, tg = v / 7;         // tg 0..15
            const int t4 = tg * 4;
            const float* xb = sxT + t4;
            const float* wb = sWT + 32 + 4 * cpos2;
            float4 acc[4] = {{0,0,0,0},{0,0,0,0},{0,0,0,0},{0,0,0,0}};
            #pragma unroll
            for (int k = 0; k < 28; k++) {
                const float4 a = *(const float4*)&xb[k * 64];
                const float4 w = *(const float4*)&wb[k * STW];
                #pragma unroll
                for (int mm = 0; mm < 4; mm++) {
                    const float wv = (mm == 0) ? w.x : (mm == 1) ? w.y : (mm == 2) ? w.z : w.w;
                    acc[mm].x = fmaf(a.x, wv, acc[mm].x);
                    acc[mm].y = fmaf(a.y, wv, acc[mm].y);
                    acc[mm].z = fmaf(a.z, wv, acc[mm].z);
                    acc[mm].w = fmaf(a.w, wv, acc[mm].w);
                }
            }
            #pragma unroll
            for (int mm = 0; mm < 4; mm++) {
                const int d0 = cpos2 + 7 * mm;
                const float* fa = (const float*)&acc[mm];
                #pragma unroll
                for (int tt = 0; tt < 4; tt++)
                    sv[(t4 + tt) * 28 + d0] = fa[tt];
            }
        }
    }
    __syncthreads();

    // ======== S2: sim = y @ x^T (256 threads, 4x4) ========
    {
        const int t4 = (tid >> 4) * 4;
        const int j4 = (tid & 15) * 4;
        const int tq = t4 >> 2;
        float4 acc[4] = {{0,0,0,0},{0,0,0,0},{0,0,0,0},{0,0,0,0}};
        #pragma unroll
        for (int k = 0; k < 28; k++) {
            const float4 q  = *(const float4*)&syT[k * 64 + 4 * ((tq ^ k) & 15)];
            const float4 kk = *(const float4*)&sxT[k * 64 + j4];
            #pragma unroll
            for (int tt = 0; tt < 4; tt++) {
                const float qv = (tt == 0) ? q.x : (tt == 1) ? q.y : (tt == 2) ? q.z : q.w;
                acc[tt].x = fmaf(qv, kk.x, acc[tt].x);
                acc[tt].y = fmaf(qv, kk.y, acc[tt].y);
                acc[tt].z = fmaf(qv, kk.z, acc[tt].z);
                acc[tt].w = fmaf(qv, kk.w, acc[tt].w);
            }
        }
        const int jq = j4 >> 2;
        #pragma unroll
        for (int tt = 0; tt < 4; tt++) {
            const int r = t4 + tt;
            *(float4*)&ssim[r * 64 + 4 * ((jq ^ (r & 15)) & 15)] = acc[tt];
        }
    }
    __syncthreads();

    // ======== S3: theta_raw[i] = sum_{j!=i} sim[i,j] * W_m1[j] ========
    if (tid < 64) {
        const int r = tid, rx = r & 15;
        const float* srow = ssim + r * 64;
        float acc = 0.f;
        #pragma unroll
        for (int j4 = 0; j4 < 64; j4 += 4) {
            const float4 s = *(const float4*)&srow[4 * (((j4 >> 2) ^ rx) & 15)];
            const float4 w = *(const float4*)&g_small[GS_WM1 + j4];
            acc = fmaf(s.x, w.x, acc); acc = fmaf(s.y, w.y, acc);
            acc = fmaf(s.z, w.z, acc); acc = fmaf(s.w, w.w, acc);
        }
        const float diag = srow[4 * (((r >> 2) ^ rx) & 15) + (r & 3)];
        acc -= diag * g_small[GS_WM1 + r];
        sth[r] = acc;
    }
    __syncthreads();

    // ======== S4: theta = W_m2b . LeakyReLU(W_m2a @ theta_raw) ========
    // thread (i = tid&63, part = tid>>6): 16 consecutive j via 4x LDG.128
    {
        float* scratch = satT;   // xT/yT region, dead after S2
        const int i = tid & 63, part = tid >> 6;
        const float4* wrow = (const float4*)(W_m2a + i * 64 + part * 16);
        const float* thp = sth + part * 16;
        float acc = 0.f;
        #pragma unroll
        for (int q = 0; q < 4; q++) {
            const float4 w = wrow[q];
            acc = fmaf(w.x, thp[q * 4 + 0], acc);
            acc = fmaf(w.y, thp[q * 4 + 1], acc);
            acc = fmaf(w.z, thp[q * 4 + 2], acc);
            acc = fmaf(w.w, thp[q * 4 + 3], acc);
        }
        scratch[part * 64 + i] = acc;
        __syncthreads();
        if (tid < 64) {
            float t = scratch[tid] + scratch[64 + tid] + scratch[128 + tid] + scratch[192 + tid];
            t = (t >= 0.f) ? t : 0.1f * t;
            float val = t * g_small[GS_WM2B + tid];
            #pragma unroll
            for (int o = 16; o > 0; o >>= 1)
                val += __shfl_down_sync(0xffffffffu, val, o);
            if ((tid & 31) == 0) sred[tid >> 5] = val;
        }
        __syncthreads();
    }
    const float theta = sred[0] + sred[1];

    // ======== S5: softmax, 8 lanes/row; attn transposed+swizzled ========
    // satT[j][t] at j*64 + 4*(((t>>2) ^ (j>>3)) & 15) + (t&3)
    {
        const int sub = tid & 7;
        const int rg  = tid >> 3;
        const float4 k0 = *(const float4*)&sigk[sub * 8];
        const float4 k1 = *(const float4*)&sigk[sub * 8 + 4];
        #pragma unroll
        for (int pass = 0; pass < 2; pass++) {
            const int r = rg + pass * 32;
            const int rx = r & 15;
            const float sgq = sigq[r];
            const float4 v0 = *(const float4*)&ssim[r * 64 + 4 * (((sub * 2) ^ rx) & 15)];
            const float4 v1 = *(const float4*)&ssim[r * 64 + 4 * (((sub * 2 + 1) ^ rx) & 15)];
            float s[8];
            s[0] = v0.x * (sgq * k0.x); s[1] = v0.y * (sgq * k0.y);
            s[2] = v0.z * (sgq * k0.z); s[3] = v0.w * (sgq * k0.w);
            s[4] = v1.x * (sgq * k1.x); s[5] = v1.y * (sgq * k1.y);
            s[6] = v1.z * (sgq * k1.z); s[7] = v1.w * (sgq * k1.w);
            float m = fmaxf(fmaxf(fmaxf(s[0], s[1]), fmaxf(s[2], s[3])),
                            fmaxf(fmaxf(s[4], s[5]), fmaxf(s[6], s[7])));
            m = fmaxf(m, __shfl_xor_sync(0xffffffffu, m, 1));
            m = fmaxf(m, __shfl_xor_sync(0xffffffffu, m, 2));
            m = fmaxf(m, __shfl_xor_sync(0xffffffffu, m, 4));
            float e[8];
            #pragma unroll
            for (int u = 0; u < 8; u++) e[u] = __expf(s[u] - m);
            float ss = ((e[0] + e[1]) + (e[2] + e[3])) + ((e[4] + e[5]) + (e[6] + e[7]));
            ss += __shfl_xor_sync(0xffffffffu, ss, 1);
            ss += __shfl_xor_sync(0xffffffffu, ss, 2);
            ss += __shfl_xor_sync(0xffffffffu, ss, 4);
            const float inv = 1.0f / ss;
            float* sbase = satT + (sub * 8) * 64 + 4 * (((r >> 2) ^ sub) & 15) + (r & 3);
            #pragma unroll
            for (int jj = 0; jj < 8; jj++)
                sbase[jj * 64] = (s[jj] > theta) ? e[jj] * inv : 0.f;
        }
    }
    __syncthreads();

    // ======== S6: out = attn @ V' + b_out. 112 threads, 4t x 4d ========
    if (tid < 112) {
        const int tgrp = tid / 7, dpos = tid % 7;
        const int t4 = tgrp * 4, d4 = dpos * 4;
        const float* vb = sv + d4;
        float4 acc[4] = {{0,0,0,0},{0,0,0,0},{0,0,0,0},{0,0,0,0}};
        #pragma unroll
        for (int j = 0; j < 64; j++) {
            const float4 at = *(const float4*)&satT[j * 64 + 4 * ((tgrp ^ (j >> 3)) & 15)];
            const float4 vv = *(const float4*)&vb[j * 28];
            #pragma unroll
            for (int tt = 0; tt < 4; tt++) {
                const float av = (tt == 0) ? at.x : (tt == 1) ? at.y : (tt == 2) ? at.z : at.w;
                acc[tt].x = fmaf(av, vv.x, acc[tt].x);
                acc[tt].y = fmaf(av, vv.y, acc[tt].y);
                acc[tt].z = fmaf(av, vv.z, acc[tt].z);
                acc[tt].w = fmaf(av, vv.w, acc[tt].w);
            }
        }
        const float4 bb = *(const float4*)&g_small[GS_BOUT + d4];
        #pragma unroll
        for (int tt = 0; tt < 4; tt++) {
            const int t = t4 + tt;
            float* ob = out + (size_t)Bi * B_STR + (wh * 8 + (t >> 3)) * H_STR
                        + (ww * 8 + (t & 7)) * 28 + d4;
            *(float4*)ob = make_float4(acc[tt].x + bb.x, acc[tt].y + bb.y,
                                       acc[tt].z + bb.z, acc[tt].w + bb.w);
        }
    }
}

extern "C" void kernel_launch(void* const* d_in, const int* in_sizes, int n_in,
                              void* d_out, int out_size) {
    (void)in_sizes; (void)n_in; (void)out_size;
    cudaFuncSetAttribute(ipb_kernel, cudaFuncAttributeMaxDynamicSharedMemorySize, SM_BYTES);
    prep_kernel<<<16, TPB>>>(
        (const float*)d_in[1],   // W_qk
        (const float*)d_in[2],   // W_v
        (const float*)d_in[3],   // W_out
        (const float*)d_in[4],   // b_out
        (const float*)d_in[5],   // W_pcq
        (const float*)d_in[6],   // b_pcq
        (const float*)d_in[7],   // W_pck
        (const float*)d_in[8],   // b_pck
        (const float*)d_in[9],   // W_m1
        (const float*)d_in[11]); // W_m2b
    ipb_kernel<<<8192, TPB, SM_BYTES>>>(
        (const float*)d_in[0],   // x
        (const float*)d_in[10],  // W_m2a
        (float*)d_out);
}

// round 15
// speedup vs baseline: 1.1276x; 1.1276x over previous
#include <cuda_runtime.h>

// ---------------------------------------------------------------------------
// IPB windowed inhibition attention, fp32. Round 15 (= R12 + packed W_m2a):
//  - Q/K eliminated: sim = x (W_q^T W_k) x^T; sigma folded into S1;
//    V' = x (W_out W_v)^T; 4x4 tiles; 5 CTAs/SM, 48-reg cap
//  - small weights: uniform reads via __constant__, divergent via LDG
//  - S4: W_m2a packed [j/4][i][4] -> 4 coalesced LDG.128 per thread
// One CTA per (window, B): 8192 CTAs x 256 threads.
// ---------------------------------------------------------------------------

#define TPB 256

namespace {
constexpr int H_STR = 256 * 28;
constexpr int B_STR = 256 * 256 * 28;
constexpr int STW = 60;     // sWT [28][60]

// layout (floats)
constexpr int OFF_XT  = 0;       // [28][64] x^T (plain)
constexpr int OFF_YT  = 1792;    // [28][64] y^T (swizzled)
constexpr int OFF_WT  = 3584;    // [28][60] permuted weights   (ends 5264)
constexpr int OFF_V   = 5264;    // [64][28] V'                 (ends 7056)
constexpr int OFF_SIM = 7056;    // [64][64] swizzled           (ends 11152)
constexpr int OFF_AT  = 0;       // attnT [64][64] alias (xT/yT dead after S2)
constexpr int OFF_SGQ = 11152;
constexpr int OFF_SGK = 11216;
constexpr int OFF_TH  = 11280;
constexpr int OFF_RED = 11344;
constexpr int SM_FLOATS = 11348;
constexpr int SM_BYTES  = SM_FLOATS * 4;   // 45392 B -> 5 CTAs/SM

// g_small layout
constexpr int GS_BOUT = 0;     // 28
constexpr int GS_WM1  = 32;    // 64
constexpr int GS_WM2B = 96;    // 64
constexpr int GS_BPCQ = 160;
constexpr int GS_BPCK = 161;
constexpr int GS_TOTAL = 176;

// W column blocks (permuted for single-float4 thread loads):
//  block1 (32 logical cols, cpos 0..7): c = cpos + 8*mm
//    c: 0..27 = M columns (y) | 28 sigma_q | 29 sigma_k | 30,31 pads
//    cp(c) = 4*(c % 8) + c/8
//  block2 (28 V' cols, cpos2 0..6): c2 = cpos2 + 7*mm, cp = 32 + 4*(c2%7) + c2/7
}

__device__ __align__(16) float g_WT[28 * STW];
__device__ __align__(16) float g_Wm2a4[64 * 64];   // [j/4][i][j%4] packed
__device__ __align__(16) float g_small[GS_TOTAL];
__constant__ __align__(16) float c_small[GS_TOTAL];

__global__ void __launch_bounds__(TPB) prep_kernel(
    const float* __restrict__ W_qk,   // [56,28]
    const float* __restrict__ W_v,    // [28,28]
    const float* __restrict__ W_out,  // [28,28]
    const float* __restrict__ W_m2a,  // [64,64]
    const float* __restrict__ b_out,  // [28]
    const float* __restrict__ W_pcq,  // [28]
    const float* __restrict__ b_pcq,  // [1]
    const float* __restrict__ W_pck,  // [28]
    const float* __restrict__ b_pck,  // [1]
    const float* __restrict__ W_m1,   // [64]
    const float* __restrict__ W_m2b)  // [64]
{
    const int gtid = blockIdx.x * TPB + threadIdx.x;
    const int gstep = gridDim.x * TPB;
    // M[e][f] = sum_r W_q[r][e] * W_k[r][f]  -> block1 col f
    for (int i = gtid; i < 784; i += gstep) {
        const int e = i / 28, f = i % 28;
        float acc = 0.f;
        #pragma unroll 7
        for (int r = 0; r < 28; r++)
            acc = fmaf(W_qk[r * 28 + e], W_qk[(28 + r) * 28 + f], acc);
        g_WT[e * STW + 4 * (f % 8) + (f / 8)] = acc;
    }
    // V' = W_out @ W_v  -> block2
    for (int i = gtid; i < 784; i += gstep) {
        const int c = i / 28, e = i % 28;
        float acc = 0.f;
        #pragma unroll 7
        for (int d = 0; d < 28; d++)
            acc = fmaf(W_out[c * 28 + d], W_v[d * 28 + e], acc);
        g_WT[e * STW + 32 + 4 * (c % 7) + (c / 7)] = acc;
    }
    // sigma columns (wx = W^T w_pc) + zero pads
    for (int i = gtid; i < 112; i += gstep) {
        const int e = i % 28, which = i / 28;
        if (which < 2) {
            const float* wp = (which == 0) ? W_pcq : W_pck;
            const int coff = (which == 0) ? 0 : 28;
            float acc = 0.f;
            #pragma unroll 7
            for (int c = 0; c < 28; c++)
                acc = fmaf(wp[c], W_qk[(coff + c) * 28 + e], acc);
            g_WT[e * STW + ((which == 0) ? 19 : 23)] = acc;  // cp(28)=19, cp(29)=23
        } else {
            g_WT[e * STW + ((which == 2) ? 27 : 31)] = 0.f;  // cp(30)=27, cp(31)=31
        }
    }
    // W_m2a packed: element (i, j) -> (j>>2)*256 + i*4 + (j&3)
    for (int idx = gtid; idx < 4096; idx += gstep) {
        const int i = idx >> 6, j = idx & 63;
        g_Wm2a4[(j >> 2) * 256 + i * 4 + (j & 3)] = W_m2a[idx];
    }
    // pack small vectors
    if (blockIdx.x == 0) {
        const int t = threadIdx.x;
        if (t < 28) g_small[GS_BOUT + t] = b_out[t];
        else if (t < 92)  g_small[GS_WM1  + t - 28] = W_m1[t - 28];
        else if (t < 156) g_small[GS_WM2B + t - 92] = W_m2b[t - 92];
        else if (t == 156) g_small[GS_BPCQ] = b_pcq[0];
        else if (t == 157) g_small[GS_BPCK] = b_pck[0];
    }
}

__global__ void __launch_bounds__(TPB, 5) ipb_kernel(
    const float* __restrict__ x,
    float* __restrict__ out)
{
    extern __shared__ float sm[];
    float* sxT  = sm + OFF_XT;
    float* syT  = sm + OFF_YT;
    float* sWT  = sm + OFF_WT;
    float* sv   = sm + OFF_V;
    float* ssim = sm + OFF_SIM;
    float* satT = sm + OFF_AT;
    float* sigq = sm + OFF_SGQ;
    float* sigk = sm + OFF_SGK;
    float* sth  = sm + OFF_TH;
    float* sred = sm + OFF_RED;

    const int tid  = threadIdx.x;
    const int widx = blockIdx.x & 1023;
    const int Bi   = blockIdx.x >> 10;
    const int wh = widx >> 5, ww = widx & 31;
    const float* xbase = x + (size_t)Bi * B_STR + wh * 8 * H_STR + ww * 8 * 28;

    // ======== S0: x transpose + weight copy ========
    {
        {
            const int r = tid & 63, c4 = (tid >> 6) * 4;
            const float4 v = *(const float4*)(xbase + (r >> 3) * H_STR + (r & 7) * 28 + c4);
            sxT[(c4 + 0) * 64 + r] = v.x;
            sxT[(c4 + 1) * 64 + r] = v.y;
            sxT[(c4 + 2) * 64 + r] = v.z;
            sxT[(c4 + 3) * 64 + r] = v.w;
        }
        if (tid < 192) {
            const int i = tid + 256;
            const int r = i & 63, c4 = (i >> 6) * 4;
            const float4 v = *(const float4*)(xbase + (r >> 3) * H_STR + (r & 7) * 28 + c4);
            sxT[(c4 + 0) * 64 + r] = v.x;
            sxT[(c4 + 1) * 64 + r] = v.y;
            sxT[(c4 + 2) * 64 + r] = v.z;
            sxT[(c4 + 3) * 64 + r] = v.w;
        }
        ((float4*)sWT)[tid] = ((const float4*)g_WT)[tid];
        if (tid < 164)
            ((float4*)sWT)[tid + 256] = ((const float4*)g_WT)[tid + 256];
    }
    __syncthreads();

    // ======== S1: [y | sigma | V'] = x @ [M | wx | W_vo^T] ========
    // 240 units: u<128 block1 (t-fast), u>=128 block2 (V, cpos-fast)
    if (tid < 240) {
        if (tid < 128) {
            const int t16 = tid & 15, cpos = tid >> 4;   // cpos 0..7
            const int t4 = t16 * 4;
            const float* xb = sxT + t4;
            const float* wb = sWT + 4 * cpos;
            float4 acc[4] = {{0,0,0,0},{0,0,0,0},{0,0,0,0},{0,0,0,0}};
            #pragma unroll
            for (int k = 0; k < 28; k++) {
                const float4 a = *(const float4*)&xb[k * 64];
                const float4 w = *(const float4*)&wb[k * STW];
                #pragma unroll
                for (int mm = 0; mm < 4; mm++) {
                    const float wv = (mm == 0) ? w.x : (mm == 1) ? w.y : (mm == 2) ? w.z : w.w;
                    acc[mm].x = fmaf(a.x, wv, acc[mm].x);
                    acc[mm].y = fmaf(a.y, wv, acc[mm].y);
                    acc[mm].z = fmaf(a.z, wv, acc[mm].z);
                    acc[mm].w = fmaf(a.w, wv, acc[mm].w);
                }
            }
            #pragma unroll
            for (int mm = 0; mm < 4; mm++) {
                const int c = cpos + 8 * mm;
                const float* fa = (const float*)&acc[mm];
                if (c < 28) {
                    *(float4*)&syT[c * 64 + 4 * ((t16 ^ c) & 15)] = acc[mm];
                } else if (c == 28) {
                    const float bq = c_small[GS_BPCQ];
                    #pragma unroll
                    for (int tt = 0; tt < 4; tt++) sigq[t4 + tt] = fa[tt] + bq;
                } else if (c == 29) {
                    const float bk = c_small[GS_BPCK];
                    #pragma unroll
                    for (int tt = 0; tt < 4; tt++) sigk[t4 + tt] = fa[tt] + bk;
                }
            }
        } else {
            const int v = tid - 128;                     // 0..111
            const int cpos2 = v % 7, tg = v / 7;         // tg 0..15
            const int t4 = tg * 4;
            const float* xb = sxT + t4;
            const float* wb = sWT + 32 + 4 * cpos2;
            float4 acc[4] = {{0,0,0,0},{0,0,0,0},{0,0,0,0},{0,0,0,0}};
            #pragma unroll
            for (int k = 0; k < 28; k++) {
                const float4 a = *(const float4*)&xb[k * 64];
                const float4 w = *(const float4*)&wb[k * STW];
                #pragma unroll
                for (int mm = 0; mm < 4; mm++) {
                    const float wv = (mm == 0) ? w.x : (mm == 1) ? w.y : (mm == 2) ? w.z : w.w;
                    acc[mm].x = fmaf(a.x, wv, acc[mm].x);
                    acc[mm].y = fmaf(a.y, wv, acc[mm].y);
                    acc[mm].z = fmaf(a.z, wv, acc[mm].z);
                    acc[mm].w = fmaf(a.w, wv, acc[mm].w);
                }
            }
            #pragma unroll
            for (int mm = 0; mm < 4; mm++) {
                const int d0 = cpos2 + 7 * mm;
                const float* fa = (const float*)&acc[mm];
                #pragma unroll
                for (int tt = 0; tt < 4; tt++)
                    sv[(t4 + tt) * 28 + d0] = fa[tt];
            }
        }
    }
    __syncthreads();

    // ======== S2: sim = y @ x^T (256 threads, 4x4) ========
    {
        const int t4 = (tid >> 4) * 4;
        const int j4 = (tid & 15) * 4;
        const int tq = t4 >> 2;
        float4 acc[4] = {{0,0,0,0},{0,0,0,0},{0,0,0,0},{0,0,0,0}};
        #pragma unroll
        for (int k = 0; k < 28; k++) {
            const float4 q  = *(const float4*)&syT[k * 64 + 4 * ((tq ^ k) & 15)];
            const float4 kk = *(const float4*)&sxT[k * 64 + j4];
            #pragma unroll
            for (int tt = 0; tt < 4; tt++) {
                const float qv = (tt == 0) ? q.x : (tt == 1) ? q.y : (tt == 2) ? q.z : q.w;
                acc[tt].x = fmaf(qv, kk.x, acc[tt].x);
                acc[tt].y = fmaf(qv, kk.y, acc[tt].y);
                acc[tt].z = fmaf(qv, kk.z, acc[tt].z);
                acc[tt].w = fmaf(qv, kk.w, acc[tt].w);
            }
        }
        const int jq = j4 >> 2;
        #pragma unroll
        for (int tt = 0; tt < 4; tt++) {
            const int r = t4 + tt;
            *(float4*)&ssim[r * 64 + 4 * ((jq ^ (r & 15)) & 15)] = acc[tt];
        }
    }
    __syncthreads();

    // ======== S3: theta_raw[i] = sum_{j!=i} sim[i,j] * W_m1[j] ========
    if (tid < 64) {
        const int r = tid, rx = r & 15;
        const float* srow = ssim + r * 64;
        float acc = 0.f;
        #pragma unroll
        for (int j4 = 0; j4 < 64; j4 += 4) {
            const float4 s = *(const float4*)&srow[4 * (((j4 >> 2) ^ rx) & 15)];
            const float4 w = *(const float4*)&c_small[GS_WM1 + j4];
            acc = fmaf(s.x, w.x, acc); acc = fmaf(s.y, w.y, acc);
            acc = fmaf(s.z, w.z, acc); acc = fmaf(s.w, w.w, acc);
        }
        const float diag = srow[4 * (((r >> 2) ^ rx) & 15) + (r & 3)];
        acc -= diag * g_small[GS_WM1 + r];   // divergent -> LDG
        sth[r] = acc;
    }
    __syncthreads();

    // ======== S4: theta = W_m2b . LeakyReLU(W_m2a @ theta_raw) ========
    // packed layout: 4 coalesced LDG.128 per thread (lane i -> offset i*4)
    {
        float* scratch = satT;   // xT/yT region, dead after S2
        const int i = tid & 63, part = tid >> 6;
        const float* thp = sth + part * 16;
        float acc = 0.f;
        #pragma unroll
        for (int q = 0; q < 4; q++) {
            const float4 w = *(const float4*)&g_Wm2a4[(part * 4 + q) * 256 + i * 4];
            acc = fmaf(w.x, thp[q * 4 + 0], acc);
            acc = fmaf(w.y, thp[q * 4 + 1], acc);
            acc = fmaf(w.z, thp[q * 4 + 2], acc);
            acc = fmaf(w.w, thp[q * 4 + 3], acc);
        }
        scratch[part * 64 + i] = acc;
        __syncthreads();
        if (tid < 64) {
            float t = scratch[tid] + scratch[64 + tid] + scratch[128 + tid] + scratch[192 + tid];
            t = (t >= 0.f) ? t : 0.1f * t;
            float val = t * g_small[GS_WM2B + tid];   // divergent -> LDG
            #pragma unroll
            for (int o = 16; o > 0; o >>= 1)
                val += __shfl_down_sync(0xffffffffu, val, o);
            if ((tid & 31) == 0) sred[tid >> 5] = val;
        }
        __syncthreads();
    }
    const float theta = sred[0] + sred[1];

    // ======== S5: softmax, 8 lanes/row; attn transposed+swizzled ========
    // satT[j][t] at j*64 + 4*(((t>>2) ^ (j>>3)) & 15) + (t&3)
    {
        const int sub = tid & 7;
        const int rg  = tid >> 3;
        const float4 k0 = *(const float4*)&sigk[sub * 8];
        const float4 k1 = *(const float4*)&sigk[sub * 8 + 4];
        #pragma unroll
        for (int pass = 0; pass < 2; pass++) {
            const int r = rg + pass * 32;
            const int rx = r & 15;
            const float sgq = sigq[r];
            const float4 v0 = *(const float4*)&ssim[r * 64 + 4 * (((sub * 2) ^ rx) & 15)];
            const float4 v1 = *(const float4*)&ssim[r * 64 + 4 * (((sub * 2 + 1) ^ rx) & 15)];
            float s[8];
            s[0] = v0.x * (sgq * k0.x); s[1] = v0.y * (sgq * k0.y);
            s[2] = v0.z * (sgq * k0.z); s[3] = v0.w * (sgq * k0.w);
            s[4] = v1.x * (sgq * k1.x); s[5] = v1.y * (sgq * k1.y);
            s[6] = v1.z * (sgq * k1.z); s[7] = v1.w * (sgq * k1.w);
            float m = fmaxf(fmaxf(fmaxf(s[0], s[1]), fmaxf(s[2], s[3])),
                            fmaxf(fmaxf(s[4], s[5]), fmaxf(s[6], s[7])));
            m = fmaxf(m, __shfl_xor_sync(0xffffffffu, m, 1));
            m = fmaxf(m, __shfl_xor_sync(0xffffffffu, m, 2));
            m = fmaxf(m, __shfl_xor_sync(0xffffffffu, m, 4));
            float e[8];
            #pragma unroll
            for (int u = 0; u < 8; u++) e[u] = __expf(s[u] - m);
            float ss = ((e[0] + e[1]) + (e[2] + e[3])) + ((e[4] + e[5]) + (e[6] + e[7]));
            ss += __shfl_xor_sync(0xffffffffu, ss, 1);
            ss += __shfl_xor_sync(0xffffffffu, ss, 2);
            ss += __shfl_xor_sync(0xffffffffu, ss, 4);
            const float inv = 1.0f / ss;
            float* sbase = satT + (sub * 8) * 64 + 4 * (((r >> 2) ^ sub) & 15) + (r & 3);
            #pragma unroll
            for (int jj = 0; jj < 8; jj++)
                sbase[jj * 64] = (s[jj] > theta) ? e[jj] * inv : 0.f;
        }
    }
    __syncthreads();

    // ======== S6: out = attn @ V' + b_out. 112 threads, 4t x 4d ========
    if (tid < 112) {
        const int tgrp = tid / 7, dpos = tid % 7;
        const int t4 = tgrp * 4, d4 = dpos * 4;
        const float* vb = sv + d4;
        float4 acc[4] = {{0,0,0,0},{0,0,0,0},{0,0,0,0},{0,0,0,0}};
        #pragma unroll
        for (int j = 0; j < 64; j++) {
            const float4 at = *(const float4*)&satT[j * 64 + 4 * ((tgrp ^ (j >> 3)) & 15)];
            const float4 vv = *(const float4*)&vb[j * 28];
            #pragma unroll
            for (int tt = 0; tt < 4; tt++) {
                const float av = (tt == 0) ? at.x : (tt == 1) ? at.y : (tt == 2) ? at.z : at.w;
                acc[tt].x = fmaf(av, vv.x, acc[tt].x);
                acc[tt].y = fmaf(av, vv.y, acc[tt].y);
                acc[tt].z = fmaf(av, vv.z, acc[tt].z);
                acc[tt].w = fmaf(av, vv.w, acc[tt].w);
            }
        }
        const float4 bb = *(const float4*)&g_small[GS_BOUT + d4];   // LDG
        #pragma unroll
        for (int tt = 0; tt < 4; tt++) {
            const int t = t4 + tt;
            float* ob = out + (size_t)Bi * B_STR + (wh * 8 + (t >> 3)) * H_STR
                        + (ww * 8 + (t & 7)) * 28 + d4;
            *(float4*)ob = make_float4(acc[tt].x + bb.x, acc[tt].y + bb.y,
                                       acc[tt].z + bb.z, acc[tt].w + bb.w);
        }
    }
}

extern "C" void kernel_launch(void* const* d_in, const int* in_sizes, int n_in,
                              void* d_out, int out_size) {
    (void)in_sizes; (void)n_in; (void)out_size;
    cudaFuncSetAttribute(ipb_kernel, cudaFuncAttributeMaxDynamicSharedMemorySize, SM_BYTES);
    prep_kernel<<<16, TPB>>>(
        (const float*)d_in[1],   // W_qk
        (const float*)d_in[2],   // W_v
        (const float*)d_in[3],   // W_out
        (const float*)d_in[10],  // W_m2a
        (const float*)d_in[4],   // b_out
        (const float*)d_in[5],   // W_pcq
        (const float*)d_in[6],   // b_pcq
        (const float*)d_in[7],   // W_pck
        (const float*)d_in[8],   // b_pck
        (const float*)d_in[9],   // W_m1
        (const float*)d_in[11]); // W_m2b
    void* gsp = nullptr;
    cudaGetSymbolAddress(&gsp, g_small);
    cudaMemcpyToSymbolAsync(c_small, gsp, GS_TOTAL * 4, 0, cudaMemcpyDeviceToDevice, 0);
    ipb_kernel<<<8192, TPB, SM_BYTES>>>(
        (const float*)d_in[0],   // x
        (float*)d_out);
}